// round 14
// baseline (speedup 1.0000x reference)
#include <cuda_runtime.h>
#include <cuda_fp16.h>
#include <cstdint>
#include <cstddef>

#define T_TOK 2048
#define H_DIM 2048
#define I_DIM 1024
#define E_NUM 16
#define K_TOP 4
#define NPAIR (T_TOK * K_TOP)

// ---------------- static device scratch ----------------
__device__ int    g_topk_idx[T_TOK * K_TOP];
__device__ float  g_topk_w[T_TOK * K_TOP];
__device__ int    g_counts[E_NUM];          // zero at load; re-zeroed by combine each run
__device__ int    g_off[E_NUM];
__device__ int    g_srcTok[NPAIR];
__device__ int    g_rowOf[T_TOK * K_TOP];
__device__ __half g_hh[(size_t)T_TOK * H_DIM];       // fp16 hidden [T, H]
__device__ __half g_act[(size_t)NPAIR * I_DIM];      // SwiGLU activations
__device__ __half g_dout[(size_t)NPAIR * H_DIM];     // per-pair down proj (fp16, unscaled)

// ---------------- helpers ----------------
__device__ __forceinline__ uint32_t smem_u32(const void* p) {
    return (uint32_t)__cvta_generic_to_shared(p);
}
__device__ __forceinline__ void cpa16(uint32_t s, const void* g) {
    asm volatile("cp.async.cg.shared.global [%0], [%1], 16;\n" :: "r"(s), "l"(g));
}
__device__ __forceinline__ void cp_commit() { asm volatile("cp.async.commit_group;\n"); }
__device__ __forceinline__ void cp_wait2()  { asm volatile("cp.async.wait_group 2;\n"); }
__device__ __forceinline__ void cp_wait1()  { asm volatile("cp.async.wait_group 1;\n"); }
__device__ __forceinline__ void cp_wait0()  { asm volatile("cp.async.wait_group 0;\n"); }

__device__ __forceinline__ void ldsm_x4(uint32_t& r0, uint32_t& r1, uint32_t& r2, uint32_t& r3,
                                        uint32_t addr) {
    asm volatile("ldmatrix.sync.aligned.m8n8.x4.shared.b16 {%0,%1,%2,%3}, [%4];"
                 : "=r"(r0), "=r"(r1), "=r"(r2), "=r"(r3) : "r"(addr));
}
__device__ __forceinline__ void ldsm_x4t(uint32_t& r0, uint32_t& r1, uint32_t& r2, uint32_t& r3,
                                         uint32_t addr) {
    asm volatile("ldmatrix.sync.aligned.m8n8.x4.trans.shared.b16 {%0,%1,%2,%3}, [%4];"
                 : "=r"(r0), "=r"(r1), "=r"(r2), "=r"(r3) : "r"(addr));
}
__device__ __forceinline__ void mma16816(float* d, uint32_t a0, uint32_t a1, uint32_t a2,
                                         uint32_t a3, uint32_t b0, uint32_t b1) {
    asm volatile(
        "mma.sync.aligned.m16n8k16.row.col.f32.f16.f16.f32 "
        "{%0,%1,%2,%3}, {%4,%5,%6,%7}, {%8,%9}, {%0,%1,%2,%3};"
        : "+f"(d[0]), "+f"(d[1]), "+f"(d[2]), "+f"(d[3])
        : "r"(a0), "r"(a1), "r"(a2), "r"(a3), "r"(b0), "r"(b1));
}
__device__ __forceinline__ uint4 pack8_interleave(float4 a, float4 b) {
    __half2 h0 = __floats2half2_rn(a.x, b.x);
    __half2 h1 = __floats2half2_rn(a.y, b.y);
    __half2 h2 = __floats2half2_rn(a.z, b.z);
    __half2 h3 = __floats2half2_rn(a.w, b.w);
    uint4 o;
    o.x = *(uint32_t*)&h0; o.y = *(uint32_t*)&h1;
    o.z = *(uint32_t*)&h2; o.w = *(uint32_t*)&h3;
    return o;
}
__device__ __forceinline__ uint4 pack8_linear(float4 a, float4 b) {
    __half2 h0 = __floats2half2_rn(a.x, a.y);
    __half2 h1 = __floats2half2_rn(a.z, a.w);
    __half2 h2 = __floats2half2_rn(b.x, b.y);
    __half2 h3 = __floats2half2_rn(b.z, b.w);
    uint4 o;
    o.x = *(uint32_t*)&h0; o.y = *(uint32_t*)&h1;
    o.z = *(uint32_t*)&h2; o.w = *(uint32_t*)&h3;
    return o;
}

// ---------------- router: warp per token ----------------
__global__ __launch_bounds__(128) void router_kernel(const float* __restrict__ hidden,
                                                     const float* __restrict__ gate_w) {
    int warp = threadIdx.x >> 5, lane = threadIdx.x & 31;
    int t = blockIdx.x * 4 + warp;
    const float4* hrow = (const float4*)(hidden + (size_t)t * H_DIM);
    __half2* hh = (__half2*)(g_hh + (size_t)t * H_DIM);
    float acc[E_NUM];
    #pragma unroll
    for (int e = 0; e < E_NUM; e++) acc[e] = 0.f;

    #pragma unroll 4
    for (int i = 0; i < 16; i++) {
        int idx = i * 32 + lane;
        float4 h = hrow[idx];
        hh[idx * 2]     = __floats2half2_rn(h.x, h.y);
        hh[idx * 2 + 1] = __floats2half2_rn(h.z, h.w);
        #pragma unroll
        for (int e = 0; e < E_NUM; e++) {
            float4 g = ((const float4*)(gate_w + (size_t)e * H_DIM))[idx];
            acc[e] += h.x * g.x + h.y * g.y + h.z * g.z + h.w * g.w;
        }
    }
    #pragma unroll
    for (int e = 0; e < E_NUM; e++)
        #pragma unroll
        for (int o = 16; o > 0; o >>= 1)
            acc[e] += __shfl_xor_sync(0xffffffffu, acc[e], o);

    if (lane == 0) {
        float mx = -1e30f;
        #pragma unroll
        for (int e = 0; e < E_NUM; e++) mx = fmaxf(mx, acc[e]);
        float pr[E_NUM];
        #pragma unroll
        for (int e = 0; e < E_NUM; e++) pr[e] = __expf(acc[e] - mx);
        int idx[K_TOP]; float w[K_TOP];
        #pragma unroll
        for (int k = 0; k < K_TOP; k++) {
            float bv = -1.f; int bi = 0;
            #pragma unroll
            for (int e = 0; e < E_NUM; e++) {
                bool used = false;
                for (int kk = 0; kk < k; kk++) if (idx[kk] == e) used = true;
                if (!used && pr[e] > bv) { bv = pr[e]; bi = e; }
            }
            idx[k] = bi; w[k] = bv;
        }
        float inv = 1.f / (w[0] + w[1] + w[2] + w[3]);
        #pragma unroll
        for (int k = 0; k < K_TOP; k++) {
            g_topk_idx[t * K_TOP + k] = idx[k];
            g_topk_w[t * K_TOP + k]   = w[k] * inv;
            atomicAdd(&g_counts[idx[k]], 1);
        }
    }
}

// ---------------- fill: 1024 threads, 2 rounds, deterministic ordered compaction ----------------
__global__ __launch_bounds__(1024) void fill_kernel() {
    int e = blockIdx.x;
    int start = 0;
    for (int i = 0; i < e; i++) start += g_counts[i];
    __shared__ int s_counter, s_prefix[32], s_wsum[32];
    int tid = threadIdx.x, lane = tid & 31, wid = tid >> 5;   // 32 warps
    if (tid == 0) { g_off[e] = start; s_counter = 0; }
    __syncthreads();
    #pragma unroll
    for (int base = 0; base < T_TOK; base += 1024) {
        int t = base + tid;
        int myk = -1;
        #pragma unroll
        for (int k = 0; k < K_TOP; k++) if (g_topk_idx[t * K_TOP + k] == e) myk = k;
        unsigned bal = __ballot_sync(0xffffffffu, myk >= 0);
        if (lane == 0) s_wsum[wid] = __popc(bal);
        __syncthreads();
        if (tid == 0) {
            int acc = s_counter;
            #pragma unroll
            for (int w = 0; w < 32; w++) { s_prefix[w] = acc; acc += s_wsum[w]; }
            s_counter = acc;
        }
        __syncthreads();
        if (myk >= 0) {
            int j = s_prefix[wid] + __popc(bal & ((1u << lane) - 1));
            int r = start + j;
            g_srcTok[r] = t;
            g_rowOf[t * K_TOP + myk] = r;
        }
        __syncthreads();
    }
}

// ---------------- GEMM smem layout: 4-stage ring (R8 config) ----------------
#define A_PITCH 40
#define B_PITCH 136
#define A_BYTES (128 * A_PITCH * 2)
#define STAGE_BYTES (A_BYTES + 32 * B_PITCH * 2)
#define SM_STAGE0 1024
#define N_STAGES 4
#define SM_BYTES (SM_STAGE0 + N_STAGES * STAGE_BYTES)

// ---------------- GEMM1: 128 threads, 4 warps of 64x64; B = fused-convert fp32 w1/w3 --------
__global__ __launch_bounds__(128, 2) void gemm1_kernel(const float* __restrict__ w1,
                                                       const float* __restrict__ w3) {
    int e = blockIdx.z;
    int M_e = g_counts[e];
    int mbase = blockIdx.y * 128;
    if (mbase >= M_e) return;
    int n0o = blockIdx.x * 64;
    int rstart = g_off[e] + mbase;
    int mrem = M_e - mbase; if (mrem > 128) mrem = 128;

    extern __shared__ __align__(16) char smem[];
    int* rows_s = (int*)smem;
    uint32_t sb = smem_u32(smem);
    int tid = threadIdx.x, lane = tid & 31;
    int warp = tid >> 5, wm = warp >> 1, wn = warp & 1;

    rows_s[tid] = (tid < mrem) ? g_srcTok[rstart + tid] : 0;
    __syncthreads();

    int am = tid >> 2, aseg = tid & 3;
    const __half* asrc[4]; uint32_t adst[4];
    #pragma unroll
    for (int p = 0; p < 4; p++) {
        int m = am + p * 32;
        asrc[p] = g_hh + (size_t)rows_s[m] * H_DIM + aseg * 8;
        adst[p] = sb + SM_STAGE0 + m * (A_PITCH * 2) + aseg * 16;
    }

    const float* b1p[4]; const float* b3p[4]; uint32_t bofs[4];
    #pragma unroll
    for (int p = 0; p < 4; p++) {
        int slot = tid + p * 128;
        int k = slot >> 4, i4 = slot & 15;
        size_t o = ((size_t)e * H_DIM + k) * I_DIM + n0o + i4 * 4;
        b1p[p] = w1 + o;
        b3p[p] = w3 + o;
        bofs[p] = A_BYTES + (uint32_t)(k * (B_PITCH * 2) + i4 * 16);
    }

    uint32_t aoff[4], boff[4];
    #pragma unroll
    for (int mf = 0; mf < 4; mf++)
        aoff[mf] = (wm * 64 + mf * 16 + (lane & 15)) * (A_PITCH * 2) + (lane >> 4) * 16;
    #pragma unroll
    for (int p = 0; p < 4; p++)
        boff[p] = A_BYTES + ((lane & 7) + 8 * ((lane >> 3) & 1)) * (B_PITCH * 2)
                + (wn * 64 + p * 16 + 8 * (lane >> 4)) * 2;

    float acc[4][8][4];
    #pragma unroll
    for (int i = 0; i < 4; i++)
        #pragma unroll
        for (int j = 0; j < 8; j++)
            #pragma unroll
            for (int r = 0; r < 4; r++) acc[i][j][r] = 0.f;

    auto issueA = [&](int s) {
        uint32_t so = (uint32_t)((s & 3) * STAGE_BYTES);
        size_t ka = (size_t)s * 32;
        #pragma unroll
        for (int p = 0; p < 4; p++) cpa16(adst[p] + so, asrc[p] + ka);
        cp_commit();
    };
    auto stsB = [&](int s, const float4* f1, const float4* f3) {
        uint32_t so = (uint32_t)((s & 3) * STAGE_BYTES);
        #pragma unroll
        for (int p = 0; p < 4; p++)
            *(uint4*)(smem + SM_STAGE0 + so + bofs[p]) = pack8_interleave(f1[p], f3[p]);
    };

    const int NS = H_DIM / 32;   // 64
    issueA(0); issueA(1); issueA(2);
    #pragma unroll
    for (int s = 0; s < 3; s++) {
        float4 f1[4], f3[4];
        size_t kb = (size_t)s * 32 * I_DIM;
        #pragma unroll
        for (int p = 0; p < 4; p++) { f1[p] = *(const float4*)(b1p[p] + kb);
                                      f3[p] = *(const float4*)(b3p[p] + kb); }
        stsB(s, f1, f3);
    }

    for (int s = 0; s < NS; s++) {
        float4 f1[4], f3[4];
        bool pre = (s + 3 < NS);
        if (pre) {
            size_t kb = (size_t)(s + 3) * 32 * I_DIM;
            #pragma unroll
            for (int p = 0; p < 4; p++) { f1[p] = *(const float4*)(b1p[p] + kb);
                                          f3[p] = *(const float4*)(b3p[p] + kb); }
        }
        int w = NS - 1 - s;
        if (w >= 2) cp_wait2(); else if (w == 1) cp_wait1(); else cp_wait0();
        __syncthreads();
        uint32_t sbase = sb + SM_STAGE0 + (uint32_t)((s & 3) * STAGE_BYTES);
        #pragma unroll
        for (int kk = 0; kk < 2; kk++) {
            uint32_t a[4][4], b[4][4];
            #pragma unroll
            for (int mf = 0; mf < 4; mf++)
                ldsm_x4(a[mf][0], a[mf][1], a[mf][2], a[mf][3],
                        sbase + aoff[mf] + kk * 32);
            #pragma unroll
            for (int p = 0; p < 4; p++)
                ldsm_x4t(b[p][0], b[p][1], b[p][2], b[p][3],
                         sbase + boff[p] + kk * 16 * (B_PITCH * 2));
            #pragma unroll
            for (int mf = 0; mf < 4; mf++) {
                #pragma unroll
                for (int p = 0; p < 4; p++) {
                    mma16816(acc[mf][p * 2],     a[mf][0], a[mf][1], a[mf][2], a[mf][3],
                             b[p][0], b[p][1]);
                    mma16816(acc[mf][p * 2 + 1], a[mf][0], a[mf][1], a[mf][2], a[mf][3],
                             b[p][2], b[p][3]);
                }
            }
        }
        if (pre) { issueA(s + 3); stsB(s + 3, f1, f3); }
    }

    #pragma unroll
    for (int mf = 0; mf < 4; mf++) {
        int r0 = wm * 64 + mf * 16 + (lane >> 2);
        #pragma unroll
        for (int nf = 0; nf < 8; nf++) {
            int col = n0o + wn * 32 + nf * 4 + (lane & 3);
            float x0 = acc[mf][nf][0], y0 = acc[mf][nf][1];
            float x1 = acc[mf][nf][2], y1 = acc[mf][nf][3];
            float v0 = x0 / (1.0f + __expf(-x0)) * y0;
            float v1 = x1 / (1.0f + __expf(-x1)) * y1;
            if (r0 < mrem)     g_act[(size_t)(rstart + r0) * I_DIM + col]     = __float2half(v0);
            if (r0 + 8 < mrem) g_act[(size_t)(rstart + r0 + 8) * I_DIM + col] = __float2half(v1);
        }
    }
}

// ---------------- GEMM2: 128 threads, 4 warps of 64x64; fp16 dout output ----------------
__global__ __launch_bounds__(128, 2) void gemm2_kernel(const float* __restrict__ w2) {
    int e = blockIdx.z;
    int M_e = g_counts[e];
    int mbase = blockIdx.y * 128;
    if (mbase >= M_e) return;
    int n0 = blockIdx.x * 128;
    int rstart = g_off[e] + mbase;
    int mrem = M_e - mbase; if (mrem > 128) mrem = 128;

    extern __shared__ __align__(16) char smem[];
    uint32_t sb = smem_u32(smem);
    int tid = threadIdx.x, lane = tid & 31;
    int warp = tid >> 5, wm = warp >> 1, wn = warp & 1;

    int am = tid >> 2, aseg = tid & 3;
    const __half* asrc[4]; uint32_t adst[4];
    #pragma unroll
    for (int p = 0; p < 4; p++) {
        int m = am + p * 32;
        int ar = rstart + m; if (ar >= NPAIR) ar = NPAIR - 1;
        asrc[p] = g_act + (size_t)ar * I_DIM + aseg * 8;
        adst[p] = sb + SM_STAGE0 + m * (A_PITCH * 2) + aseg * 16;
    }

    const float* bp[4]; uint32_t bofs[4];
    #pragma unroll
    for (int p = 0; p < 4; p++) {
        int slot = tid + p * 128;
        int k = slot >> 4, n8 = slot & 15;
        bp[p] = w2 + ((size_t)e * I_DIM + k) * H_DIM + n0 + n8 * 8;
        bofs[p] = A_BYTES + (uint32_t)(k * (B_PITCH * 2) + n8 * 16);
    }

    uint32_t aoff[4], boff[4];
    #pragma unroll
    for (int mf = 0; mf < 4; mf++)
        aoff[mf] = (wm * 64 + mf * 16 + (lane & 15)) * (A_PITCH * 2) + (lane >> 4) * 16;
    #pragma unroll
    for (int p = 0; p < 4; p++)
        boff[p] = A_BYTES + ((lane & 7) + 8 * ((lane >> 3) & 1)) * (B_PITCH * 2)
                + (wn * 64 + p * 16 + 8 * (lane >> 4)) * 2;

    float acc[4][8][4];
    #pragma unroll
    for (int i = 0; i < 4; i++)
        #pragma unroll
        for (int j = 0; j < 8; j++)
            #pragma unroll
            for (int r = 0; r < 4; r++) acc[i][j][r] = 0.f;

    auto issueA = [&](int s) {
        uint32_t so = (uint32_t)((s & 3) * STAGE_BYTES);
        size_t ka = (size_t)s * 32;
        #pragma unroll
        for (int p = 0; p < 4; p++) cpa16(adst[p] + so, asrc[p] + ka);
        cp_commit();
    };
    auto stsB = [&](int s, const float4* lo, const float4* hi) {
        uint32_t so = (uint32_t)((s & 3) * STAGE_BYTES);
        #pragma unroll
        for (int p = 0; p < 4; p++)
            *(uint4*)(smem + SM_STAGE0 + so + bofs[p]) = pack8_linear(lo[p], hi[p]);
    };

    const int NS = I_DIM / 32;   // 32
    issueA(0); issueA(1); issueA(2);
    #pragma unroll
    for (int s = 0; s < 3; s++) {
        float4 lo[4], hi[4];
        size_t kb = (size_t)s * 32 * H_DIM;
        #pragma unroll
        for (int p = 0; p < 4; p++) { lo[p] = *(const float4*)(bp[p] + kb);
                                      hi[p] = *(const float4*)(bp[p] + kb + 4); }
        stsB(s, lo, hi);
    }

    for (int s = 0; s < NS; s++) {
        float4 lo[4], hi[4];
        bool pre = (s + 3 < NS);
        if (pre) {
            size_t kb = (size_t)(s + 3) * 32 * H_DIM;
            #pragma unroll
            for (int p = 0; p < 4; p++) { lo[p] = *(const float4*)(bp[p] + kb);
                                          hi[p] = *(const float4*)(bp[p] + kb + 4); }
        }
        int w = NS - 1 - s;
        if (w >= 2) cp_wait2(); else if (w == 1) cp_wait1(); else cp_wait0();
        __syncthreads();
        uint32_t sbase = sb + SM_STAGE0 + (uint32_t)((s & 3) * STAGE_BYTES);
        #pragma unroll
        for (int kk = 0; kk < 2; kk++) {
            uint32_t a[4][4], b[4][4];
            #pragma unroll
            for (int mf = 0; mf < 4; mf++)
                ldsm_x4(a[mf][0], a[mf][1], a[mf][2], a[mf][3],
                        sbase + aoff[mf] + kk * 32);
            #pragma unroll
            for (int p = 0; p < 4; p++)
                ldsm_x4t(b[p][0], b[p][1], b[p][2], b[p][3],
                         sbase + boff[p] + kk * 16 * (B_PITCH * 2));
            #pragma unroll
            for (int mf = 0; mf < 4; mf++) {
                #pragma unroll
                for (int p = 0; p < 4; p++) {
                    mma16816(acc[mf][p * 2],     a[mf][0], a[mf][1], a[mf][2], a[mf][3],
                             b[p][0], b[p][1]);
                    mma16816(acc[mf][p * 2 + 1], a[mf][0], a[mf][1], a[mf][2], a[mf][3],
                             b[p][2], b[p][3]);
                }
            }
        }
        if (pre) { issueA(s + 3); stsB(s + 3, lo, hi); }
    }

    // epilogue: fp16 __half2 stores (unscaled; combine applies weights)
    #pragma unroll
    for (int mf = 0; mf < 4; mf++) {
        int r0 = wm * 64 + mf * 16 + (lane >> 2);
        #pragma unroll
        for (int nf = 0; nf < 8; nf++) {
            int col = n0 + wn * 64 + nf * 8 + (lane & 3) * 2;
            if (r0 < mrem) {
                __half2 v = __floats2half2_rn(acc[mf][nf][0], acc[mf][nf][1]);
                *(__half2*)(g_dout + (size_t)(rstart + r0) * H_DIM + col) = v;
            }
            if (r0 + 8 < mrem) {
                __half2 v = __floats2half2_rn(acc[mf][nf][2], acc[mf][nf][3]);
                *(__half2*)(g_dout + (size_t)(rstart + r0 + 8) * H_DIM + col) = v;
            }
        }
    }
}

// ---------------- combine: fp16 in, fp32 weighted sum out; also re-zero counts ----------------
__global__ __launch_bounds__(256) void combine_kernel(float* __restrict__ out) {
    int t = blockIdx.x;
    int r0 = g_rowOf[t * K_TOP + 0], r1 = g_rowOf[t * K_TOP + 1];
    int r2 = g_rowOf[t * K_TOP + 2], r3 = g_rowOf[t * K_TOP + 3];
    float w0 = g_topk_w[t * K_TOP + 0], w1 = g_topk_w[t * K_TOP + 1];
    float w2 = g_topk_w[t * K_TOP + 2], w3 = g_topk_w[t * K_TOP + 3];
    const uint4* d0 = (const uint4*)(g_dout + (size_t)r0 * H_DIM);
    const uint4* d1 = (const uint4*)(g_dout + (size_t)r1 * H_DIM);
    const uint4* d2 = (const uint4*)(g_dout + (size_t)r2 * H_DIM);
    const uint4* d3 = (const uint4*)(g_dout + (size_t)r3 * H_DIM);
    float4* o = (float4*)(out + (size_t)t * H_DIM);

    int i = threadIdx.x;                       // 256 threads, 256 chunks of 8 halves
    uint4 a = d0[i], b = d1[i], c = d2[i], d = d3[i];
    const uint32_t* aw = (const uint32_t*)&a;
    const uint32_t* bw = (const uint32_t*)&b;
    const uint32_t* cw = (const uint32_t*)&c;
    const uint32_t* dw = (const uint32_t*)&d;
    float res[8];
    #pragma unroll
    for (int j = 0; j < 4; j++) {
        float2 fa = __half22float2(*(const __half2*)&aw[j]);
        float2 fb = __half22float2(*(const __half2*)&bw[j]);
        float2 fc = __half22float2(*(const __half2*)&cw[j]);
        float2 fd = __half22float2(*(const __half2*)&dw[j]);
        res[j * 2]     = w0 * fa.x + w1 * fb.x + w2 * fc.x + w3 * fd.x;
        res[j * 2 + 1] = w0 * fa.y + w1 * fb.y + w2 * fc.y + w3 * fd.y;
    }
    o[i * 2]     = make_float4(res[0], res[1], res[2], res[3]);
    o[i * 2 + 1] = make_float4(res[4], res[5], res[6], res[7]);

    // last kernel in the sequence: reset counts for the next graph replay
    if (t == 0 && threadIdx.x < E_NUM) g_counts[threadIdx.x] = 0;
}

// ---------------- launch ----------------
extern "C" void kernel_launch(void* const* d_in, const int* in_sizes, int n_in,
                              void* d_out, int out_size) {
    const float* hidden = (const float*)d_in[0];
    const float* gate_w = (const float*)d_in[1];
    const float* w1     = (const float*)d_in[2];
    const float* w3     = (const float*)d_in[3];
    const float* w2     = (const float*)d_in[4];
    float* out = (float*)d_out;

    cudaFuncSetAttribute(gemm1_kernel, cudaFuncAttributeMaxDynamicSharedMemorySize, SM_BYTES);
    cudaFuncSetAttribute(gemm2_kernel, cudaFuncAttributeMaxDynamicSharedMemorySize, SM_BYTES);

    router_kernel<<<T_TOK / 4, 128>>>(hidden, gate_w);           // 1
    fill_kernel<<<E_NUM, 1024>>>();                              // 2
    gemm1_kernel<<<dim3(I_DIM / 64, T_TOK / 128, E_NUM), 128, SM_BYTES>>>(w1, w3);  // 3
    gemm2_kernel<<<dim3(H_DIM / 128, T_TOK / 128, E_NUM), 128, SM_BYTES>>>(w2);     // 4
    combine_kernel<<<T_TOK, 256>>>(out);                         // 5
}

// round 16
// speedup vs baseline: 1.0205x; 1.0205x over previous
#include <cuda_runtime.h>
#include <cuda_fp16.h>
#include <cstdint>
#include <cstddef>

#define T_TOK 2048
#define H_DIM 2048
#define I_DIM 1024
#define E_NUM 16
#define K_TOP 4
#define CAP   2048                      // per-expert bucket capacity (worst case)

// ---------------- static device scratch ----------------
__device__ float  g_topk_w[T_TOK * K_TOP];
__device__ int    g_counts[E_NUM];          // zero at load; re-zeroed by combine each run
__device__ int    g_srcTok[E_NUM * CAP];
__device__ int    g_rowOf[T_TOK * K_TOP];
__device__ __half g_hh[(size_t)T_TOK * H_DIM];          // fp16 hidden [T, H]
__device__ __half g_act[(size_t)E_NUM * CAP * I_DIM];   // SwiGLU activations (bucketed)
__device__ __half g_dout[(size_t)E_NUM * CAP * H_DIM];  // per-pair down proj (fp16, unscaled)

// ---------------- helpers ----------------
__device__ __forceinline__ uint32_t smem_u32(const void* p) {
    return (uint32_t)__cvta_generic_to_shared(p);
}
__device__ __forceinline__ void cpa16(uint32_t s, const void* g) {
    asm volatile("cp.async.cg.shared.global [%0], [%1], 16;\n" :: "r"(s), "l"(g));
}
__device__ __forceinline__ void cp_commit() { asm volatile("cp.async.commit_group;\n"); }
__device__ __forceinline__ void cp_wait2()  { asm volatile("cp.async.wait_group 2;\n"); }
__device__ __forceinline__ void cp_wait1()  { asm volatile("cp.async.wait_group 1;\n"); }
__device__ __forceinline__ void cp_wait0()  { asm volatile("cp.async.wait_group 0;\n"); }

__device__ __forceinline__ void ldsm_x4(uint32_t& r0, uint32_t& r1, uint32_t& r2, uint32_t& r3,
                                        uint32_t addr) {
    asm volatile("ldmatrix.sync.aligned.m8n8.x4.shared.b16 {%0,%1,%2,%3}, [%4];"
                 : "=r"(r0), "=r"(r1), "=r"(r2), "=r"(r3) : "r"(addr));
}
__device__ __forceinline__ void ldsm_x4t(uint32_t& r0, uint32_t& r1, uint32_t& r2, uint32_t& r3,
                                         uint32_t addr) {
    asm volatile("ldmatrix.sync.aligned.m8n8.x4.trans.shared.b16 {%0,%1,%2,%3}, [%4];"
                 : "=r"(r0), "=r"(r1), "=r"(r2), "=r"(r3) : "r"(addr));
}
__device__ __forceinline__ void mma16816(float* d, uint32_t a0, uint32_t a1, uint32_t a2,
                                         uint32_t a3, uint32_t b0, uint32_t b1) {
    asm volatile(
        "mma.sync.aligned.m16n8k16.row.col.f32.f16.f16.f32 "
        "{%0,%1,%2,%3}, {%4,%5,%6,%7}, {%8,%9}, {%0,%1,%2,%3};"
        : "+f"(d[0]), "+f"(d[1]), "+f"(d[2]), "+f"(d[3])
        : "r"(a0), "r"(a1), "r"(a2), "r"(a3), "r"(b0), "r"(b1));
}
__device__ __forceinline__ uint4 pack8_interleave(float4 a, float4 b) {
    __half2 h0 = __floats2half2_rn(a.x, b.x);
    __half2 h1 = __floats2half2_rn(a.y, b.y);
    __half2 h2 = __floats2half2_rn(a.z, b.z);
    __half2 h3 = __floats2half2_rn(a.w, b.w);
    uint4 o;
    o.x = *(uint32_t*)&h0; o.y = *(uint32_t*)&h1;
    o.z = *(uint32_t*)&h2; o.w = *(uint32_t*)&h3;
    return o;
}
__device__ __forceinline__ uint4 pack8_linear(float4 a, float4 b) {
    __half2 h0 = __floats2half2_rn(a.x, a.y);
    __half2 h1 = __floats2half2_rn(a.z, a.w);
    __half2 h2 = __floats2half2_rn(b.x, b.y);
    __half2 h3 = __floats2half2_rn(b.z, b.w);
    uint4 o;
    o.x = *(uint32_t*)&h0; o.y = *(uint32_t*)&h1;
    o.z = *(uint32_t*)&h2; o.w = *(uint32_t*)&h3;
    return o;
}

// ---------------- router: warp per token; direct bucket slot assignment ----------------
__global__ __launch_bounds__(128) void router_kernel(const float* __restrict__ hidden,
                                                     const float* __restrict__ gate_w) {
    int warp = threadIdx.x >> 5, lane = threadIdx.x & 31;
    int t = blockIdx.x * 4 + warp;
    const float4* hrow = (const float4*)(hidden + (size_t)t * H_DIM);
    __half2* hh = (__half2*)(g_hh + (size_t)t * H_DIM);
    float acc[E_NUM];
    #pragma unroll
    for (int e = 0; e < E_NUM; e++) acc[e] = 0.f;

    #pragma unroll 4
    for (int i = 0; i < 16; i++) {
        int idx = i * 32 + lane;
        float4 h = hrow[idx];
        hh[idx * 2]     = __floats2half2_rn(h.x, h.y);
        hh[idx * 2 + 1] = __floats2half2_rn(h.z, h.w);
        #pragma unroll
        for (int e = 0; e < E_NUM; e++) {
            float4 g = ((const float4*)(gate_w + (size_t)e * H_DIM))[idx];
            acc[e] += h.x * g.x + h.y * g.y + h.z * g.z + h.w * g.w;
        }
    }
    #pragma unroll
    for (int e = 0; e < E_NUM; e++)
        #pragma unroll
        for (int o = 16; o > 0; o >>= 1)
            acc[e] += __shfl_xor_sync(0xffffffffu, acc[e], o);

    if (lane == 0) {
        float mx = -1e30f;
        #pragma unroll
        for (int e = 0; e < E_NUM; e++) mx = fmaxf(mx, acc[e]);
        float pr[E_NUM];
        #pragma unroll
        for (int e = 0; e < E_NUM; e++) pr[e] = __expf(acc[e] - mx);
        int idx[K_TOP]; float w[K_TOP];
        #pragma unroll
        for (int k = 0; k < K_TOP; k++) {
            float bv = -1.f; int bi = 0;
            #pragma unroll
            for (int e = 0; e < E_NUM; e++) {
                bool used = false;
                for (int kk = 0; kk < k; kk++) if (idx[kk] == e) used = true;
                if (!used && pr[e] > bv) { bv = pr[e]; bi = e; }
            }
            idx[k] = bi; w[k] = bv;
        }
        float inv = 1.f / (w[0] + w[1] + w[2] + w[3]);
        #pragma unroll
        for (int k = 0; k < K_TOP; k++) {
            int e = idx[k];
            int slot = atomicAdd(&g_counts[e], 1);   // order-free: row math is slot-invariant
            int r = e * CAP + slot;
            g_srcTok[r] = t;
            g_rowOf[t * K_TOP + k] = r;
            g_topk_w[t * K_TOP + k] = w[k] * inv;
        }
    }
}

// ---------------- GEMM smem layout: 4-stage ring (R8 config) ----------------
#define A_PITCH 40
#define B_PITCH 136
#define A_BYTES (128 * A_PITCH * 2)
#define STAGE_BYTES (A_BYTES + 32 * B_PITCH * 2)
#define SM_STAGE0 1024
#define N_STAGES 4
#define SM_BYTES (SM_STAGE0 + N_STAGES * STAGE_BYTES)

// ---------------- GEMM1: 128 threads, 4 warps of 64x64; B = fused-convert fp32 w1/w3 --------
__global__ __launch_bounds__(128, 2) void gemm1_kernel(const float* __restrict__ w1,
                                                       const float* __restrict__ w3) {
    int e = blockIdx.z;
    int M_e = g_counts[e];
    int mbase = blockIdx.y * 128;
    if (mbase >= M_e) return;
    int n0o = blockIdx.x * 64;
    int rstart = e * CAP + mbase;
    int mrem = M_e - mbase; if (mrem > 128) mrem = 128;

    extern __shared__ __align__(16) char smem[];
    int* rows_s = (int*)smem;
    uint32_t sb = smem_u32(smem);
    int tid = threadIdx.x, lane = tid & 31;
    int warp = tid >> 5, wm = warp >> 1, wn = warp & 1;

    rows_s[tid] = (tid < mrem) ? g_srcTok[rstart + tid] : 0;
    __syncthreads();

    int am = tid >> 2, aseg = tid & 3;
    const __half* asrc[4]; uint32_t adst[4];
    #pragma unroll
    for (int p = 0; p < 4; p++) {
        int m = am + p * 32;
        asrc[p] = g_hh + (size_t)rows_s[m] * H_DIM + aseg * 8;
        adst[p] = sb + SM_STAGE0 + m * (A_PITCH * 2) + aseg * 16;
    }

    const float* b1p[4]; const float* b3p[4]; uint32_t bofs[4];
    #pragma unroll
    for (int p = 0; p < 4; p++) {
        int slot = tid + p * 128;
        int k = slot >> 4, i4 = slot & 15;
        size_t o = ((size_t)e * H_DIM + k) * I_DIM + n0o + i4 * 4;
        b1p[p] = w1 + o;
        b3p[p] = w3 + o;
        bofs[p] = A_BYTES + (uint32_t)(k * (B_PITCH * 2) + i4 * 16);
    }

    uint32_t aoff[4], boff[4];
    #pragma unroll
    for (int mf = 0; mf < 4; mf++)
        aoff[mf] = (wm * 64 + mf * 16 + (lane & 15)) * (A_PITCH * 2) + (lane >> 4) * 16;
    #pragma unroll
    for (int p = 0; p < 4; p++)
        boff[p] = A_BYTES + ((lane & 7) + 8 * ((lane >> 3) & 1)) * (B_PITCH * 2)
                + (wn * 64 + p * 16 + 8 * (lane >> 4)) * 2;

    float acc[4][8][4];
    #pragma unroll
    for (int i = 0; i < 4; i++)
        #pragma unroll
        for (int j = 0; j < 8; j++)
            #pragma unroll
            for (int r = 0; r < 4; r++) acc[i][j][r] = 0.f;

    auto issueA = [&](int s) {
        uint32_t so = (uint32_t)((s & 3) * STAGE_BYTES);
        size_t ka = (size_t)s * 32;
        #pragma unroll
        for (int p = 0; p < 4; p++) cpa16(adst[p] + so, asrc[p] + ka);
        cp_commit();
    };
    auto stsB = [&](int s, const float4* f1, const float4* f3) {
        uint32_t so = (uint32_t)((s & 3) * STAGE_BYTES);
        #pragma unroll
        for (int p = 0; p < 4; p++)
            *(uint4*)(smem + SM_STAGE0 + so + bofs[p]) = pack8_interleave(f1[p], f3[p]);
    };

    const int NS = H_DIM / 32;   // 64
    issueA(0); issueA(1); issueA(2);
    #pragma unroll
    for (int s = 0; s < 3; s++) {
        float4 f1[4], f3[4];
        size_t kb = (size_t)s * 32 * I_DIM;
        #pragma unroll
        for (int p = 0; p < 4; p++) { f1[p] = *(const float4*)(b1p[p] + kb);
                                      f3[p] = *(const float4*)(b3p[p] + kb); }
        stsB(s, f1, f3);
    }

    for (int s = 0; s < NS; s++) {
        float4 f1[4], f3[4];
        bool pre = (s + 3 < NS);
        if (pre) {
            size_t kb = (size_t)(s + 3) * 32 * I_DIM;
            #pragma unroll
            for (int p = 0; p < 4; p++) { f1[p] = *(const float4*)(b1p[p] + kb);
                                          f3[p] = *(const float4*)(b3p[p] + kb); }
        }
        int w = NS - 1 - s;
        if (w >= 2) cp_wait2(); else if (w == 1) cp_wait1(); else cp_wait0();
        __syncthreads();
        uint32_t sbase = sb + SM_STAGE0 + (uint32_t)((s & 3) * STAGE_BYTES);
        #pragma unroll
        for (int kk = 0; kk < 2; kk++) {
            uint32_t a[4][4], b[4][4];
            #pragma unroll
            for (int mf = 0; mf < 4; mf++)
                ldsm_x4(a[mf][0], a[mf][1], a[mf][2], a[mf][3],
                        sbase + aoff[mf] + kk * 32);
            #pragma unroll
            for (int p = 0; p < 4; p++)
                ldsm_x4t(b[p][0], b[p][1], b[p][2], b[p][3],
                         sbase + boff[p] + kk * 16 * (B_PITCH * 2));
            #pragma unroll
            for (int mf = 0; mf < 4; mf++) {
                #pragma unroll
                for (int p = 0; p < 4; p++) {
                    mma16816(acc[mf][p * 2],     a[mf][0], a[mf][1], a[mf][2], a[mf][3],
                             b[p][0], b[p][1]);
                    mma16816(acc[mf][p * 2 + 1], a[mf][0], a[mf][1], a[mf][2], a[mf][3],
                             b[p][2], b[p][3]);
                }
            }
        }
        if (pre) { issueA(s + 3); stsB(s + 3, f1, f3); }
    }

    #pragma unroll
    for (int mf = 0; mf < 4; mf++) {
        int r0 = wm * 64 + mf * 16 + (lane >> 2);
        #pragma unroll
        for (int nf = 0; nf < 8; nf++) {
            int col = n0o + wn * 32 + nf * 4 + (lane & 3);
            float x0 = acc[mf][nf][0], y0 = acc[mf][nf][1];
            float x1 = acc[mf][nf][2], y1 = acc[mf][nf][3];
            float v0 = x0 / (1.0f + __expf(-x0)) * y0;
            float v1 = x1 / (1.0f + __expf(-x1)) * y1;
            if (r0 < mrem)     g_act[(size_t)(rstart + r0) * I_DIM + col]     = __float2half(v0);
            if (r0 + 8 < mrem) g_act[(size_t)(rstart + r0 + 8) * I_DIM + col] = __float2half(v1);
        }
    }
}

// ---------------- GEMM2: 128 threads, 4 warps of 64x64; fp16 dout output ----------------
__global__ __launch_bounds__(128, 2) void gemm2_kernel(const float* __restrict__ w2) {
    int e = blockIdx.z;
    int M_e = g_counts[e];
    int mbase = blockIdx.y * 128;
    if (mbase >= M_e) return;
    int n0 = blockIdx.x * 128;
    int rstart = e * CAP + mbase;
    int mrem = M_e - mbase; if (mrem > 128) mrem = 128;

    extern __shared__ __align__(16) char smem[];
    uint32_t sb = smem_u32(smem);
    int tid = threadIdx.x, lane = tid & 31;
    int warp = tid >> 5, wm = warp >> 1, wn = warp & 1;

    int am = tid >> 2, aseg = tid & 3;
    const __half* asrc[4]; uint32_t adst[4];
    #pragma unroll
    for (int p = 0; p < 4; p++) {
        int m = am + p * 32;
        int ar = rstart + m;                 // always < E_NUM*CAP (mbase<CAP)
        asrc[p] = g_act + (size_t)ar * I_DIM + aseg * 8;
        adst[p] = sb + SM_STAGE0 + m * (A_PITCH * 2) + aseg * 16;
    }

    const float* bp[4]; uint32_t bofs[4];
    #pragma unroll
    for (int p = 0; p < 4; p++) {
        int slot = tid + p * 128;
        int k = slot >> 4, n8 = slot & 15;
        bp[p] = w2 + ((size_t)e * I_DIM + k) * H_DIM + n0 + n8 * 8;
        bofs[p] = A_BYTES + (uint32_t)(k * (B_PITCH * 2) + n8 * 16);
    }

    uint32_t aoff[4], boff[4];
    #pragma unroll
    for (int mf = 0; mf < 4; mf++)
        aoff[mf] = (wm * 64 + mf * 16 + (lane & 15)) * (A_PITCH * 2) + (lane >> 4) * 16;
    #pragma unroll
    for (int p = 0; p < 4; p++)
        boff[p] = A_BYTES + ((lane & 7) + 8 * ((lane >> 3) & 1)) * (B_PITCH * 2)
                + (wn * 64 + p * 16 + 8 * (lane >> 4)) * 2;

    float acc[4][8][4];
    #pragma unroll
    for (int i = 0; i < 4; i++)
        #pragma unroll
        for (int j = 0; j < 8; j++)
            #pragma unroll
            for (int r = 0; r < 4; r++) acc[i][j][r] = 0.f;

    auto issueA = [&](int s) {
        uint32_t so = (uint32_t)((s & 3) * STAGE_BYTES);
        size_t ka = (size_t)s * 32;
        #pragma unroll
        for (int p = 0; p < 4; p++) cpa16(adst[p] + so, asrc[p] + ka);
        cp_commit();
    };
    auto stsB = [&](int s, const float4* lo, const float4* hi) {
        uint32_t so = (uint32_t)((s & 3) * STAGE_BYTES);
        #pragma unroll
        for (int p = 0; p < 4; p++)
            *(uint4*)(smem + SM_STAGE0 + so + bofs[p]) = pack8_linear(lo[p], hi[p]);
    };

    const int NS = I_DIM / 32;   // 32
    issueA(0); issueA(1); issueA(2);
    #pragma unroll
    for (int s = 0; s < 3; s++) {
        float4 lo[4], hi[4];
        size_t kb = (size_t)s * 32 * H_DIM;
        #pragma unroll
        for (int p = 0; p < 4; p++) { lo[p] = *(const float4*)(bp[p] + kb);
                                      hi[p] = *(const float4*)(bp[p] + kb + 4); }
        stsB(s, lo, hi);
    }

    for (int s = 0; s < NS; s++) {
        float4 lo[4], hi[4];
        bool pre = (s + 3 < NS);
        if (pre) {
            size_t kb = (size_t)(s + 3) * 32 * H_DIM;
            #pragma unroll
            for (int p = 0; p < 4; p++) { lo[p] = *(const float4*)(bp[p] + kb);
                                          hi[p] = *(const float4*)(bp[p] + kb + 4); }
        }
        int w = NS - 1 - s;
        if (w >= 2) cp_wait2(); else if (w == 1) cp_wait1(); else cp_wait0();
        __syncthreads();
        uint32_t sbase = sb + SM_STAGE0 + (uint32_t)((s & 3) * STAGE_BYTES);
        #pragma unroll
        for (int kk = 0; kk < 2; kk++) {
            uint32_t a[4][4], b[4][4];
            #pragma unroll
            for (int mf = 0; mf < 4; mf++)
                ldsm_x4(a[mf][0], a[mf][1], a[mf][2], a[mf][3],
                        sbase + aoff[mf] + kk * 32);
            #pragma unroll
            for (int p = 0; p < 4; p++)
                ldsm_x4t(b[p][0], b[p][1], b[p][2], b[p][3],
                         sbase + boff[p] + kk * 16 * (B_PITCH * 2));
            #pragma unroll
            for (int mf = 0; mf < 4; mf++) {
                #pragma unroll
                for (int p = 0; p < 4; p++) {
                    mma16816(acc[mf][p * 2],     a[mf][0], a[mf][1], a[mf][2], a[mf][3],
                             b[p][0], b[p][1]);
                    mma16816(acc[mf][p * 2 + 1], a[mf][0], a[mf][1], a[mf][2], a[mf][3],
                             b[p][2], b[p][3]);
                }
            }
        }
        if (pre) { issueA(s + 3); stsB(s + 3, lo, hi); }
    }

    // epilogue: fp16 __half2 stores (unscaled; combine applies weights)
    #pragma unroll
    for (int mf = 0; mf < 4; mf++) {
        int r0 = wm * 64 + mf * 16 + (lane >> 2);
        #pragma unroll
        for (int nf = 0; nf < 8; nf++) {
            int col = n0 + wn * 64 + nf * 8 + (lane & 3) * 2;
            if (r0 < mrem) {
                __half2 v = __floats2half2_rn(acc[mf][nf][0], acc[mf][nf][1]);
                *(__half2*)(g_dout + (size_t)(rstart + r0) * H_DIM + col) = v;
            }
            if (r0 + 8 < mrem) {
                __half2 v = __floats2half2_rn(acc[mf][nf][2], acc[mf][nf][3]);
                *(__half2*)(g_dout + (size_t)(rstart + r0 + 8) * H_DIM + col) = v;
            }
        }
    }
}

// ---------------- combine: fp16 in, fp32 weighted sum out; also re-zero counts ----------------
__global__ __launch_bounds__(256) void combine_kernel(float* __restrict__ out) {
    int t = blockIdx.x;
    int r0 = g_rowOf[t * K_TOP + 0], r1 = g_rowOf[t * K_TOP + 1];
    int r2 = g_rowOf[t * K_TOP + 2], r3 = g_rowOf[t * K_TOP + 3];
    float w0 = g_topk_w[t * K_TOP + 0], w1 = g_topk_w[t * K_TOP + 1];
    float w2 = g_topk_w[t * K_TOP + 2], w3 = g_topk_w[t * K_TOP + 3];
    const uint4* d0 = (const uint4*)(g_dout + (size_t)r0 * H_DIM);
    const uint4* d1 = (const uint4*)(g_dout + (size_t)r1 * H_DIM);
    const uint4* d2 = (const uint4*)(g_dout + (size_t)r2 * H_DIM);
    const uint4* d3 = (const uint4*)(g_dout + (size_t)r3 * H_DIM);
    float4* o = (float4*)(out + (size_t)t * H_DIM);

    int i = threadIdx.x;                       // 256 threads, 256 chunks of 8 halves
    uint4 a = d0[i], b = d1[i], c = d2[i], d = d3[i];
    const uint32_t* aw = (const uint32_t*)&a;
    const uint32_t* bw = (const uint32_t*)&b;
    const uint32_t* cw = (const uint32_t*)&c;
    const uint32_t* dw = (const uint32_t*)&d;
    float res[8];
    #pragma unroll
    for (int j = 0; j < 4; j++) {
        float2 fa = __half22float2(*(const __half2*)&aw[j]);
        float2 fb = __half22float2(*(const __half2*)&bw[j]);
        float2 fc = __half22float2(*(const __half2*)&cw[j]);
        float2 fd = __half22float2(*(const __half2*)&dw[j]);
        res[j * 2]     = w0 * fa.x + w1 * fb.x + w2 * fc.x + w3 * fd.x;
        res[j * 2 + 1] = w0 * fa.y + w1 * fb.y + w2 * fc.y + w3 * fd.y;
    }
    o[i * 2]     = make_float4(res[0], res[1], res[2], res[3]);
    o[i * 2 + 1] = make_float4(res[4], res[5], res[6], res[7]);

    // last kernel in the sequence: reset counts for the next graph replay
    if (t == 0 && threadIdx.x < E_NUM) g_counts[threadIdx.x] = 0;
}

// ---------------- launch ----------------
extern "C" void kernel_launch(void* const* d_in, const int* in_sizes, int n_in,
                              void* d_out, int out_size) {
    const float* hidden = (const float*)d_in[0];
    const float* gate_w = (const float*)d_in[1];
    const float* w1     = (const float*)d_in[2];
    const float* w3     = (const float*)d_in[3];
    const float* w2     = (const float*)d_in[4];
    float* out = (float*)d_out;

    cudaFuncSetAttribute(gemm1_kernel, cudaFuncAttributeMaxDynamicSharedMemorySize, SM_BYTES);
    cudaFuncSetAttribute(gemm2_kernel, cudaFuncAttributeMaxDynamicSharedMemorySize, SM_BYTES);

    router_kernel<<<T_TOK / 4, 128>>>(hidden, gate_w);           // 1
    gemm1_kernel<<<dim3(I_DIM / 64, CAP / 128, E_NUM), 128, SM_BYTES>>>(w1, w3);  // 2
    gemm2_kernel<<<dim3(H_DIM / 128, CAP / 128, E_NUM), 128, SM_BYTES>>>(w2);     // 3
    combine_kernel<<<T_TOK, 256>>>(out);                         // 4
}